// round 2
// baseline (speedup 1.0000x reference)
#include <cuda_runtime.h>
#include <cuda_bf16.h>

// Problem constants (from reference)
#define NN 50000
#define EE 800000
#define DIN 128
#define DHID 128
#define DOUT3 64

// ---------------- device scratch (no allocations allowed) ----------------
__device__ float g_hA[NN * DHID];      // layer-1 output
__device__ float g_hB[NN * DHID];      // layer-2 output
__device__ float g_neigh[NN * DHID];   // aggregated neighbor features
__device__ int   g_deg[NN];
__device__ int   g_off[NN + 1];
__device__ int   g_cur[NN];
__device__ int   g_csr[EE];

// ---------------- CSR build ----------------
__global__ void zero_kernel() {
    int i = blockIdx.x * blockDim.x + threadIdx.x;
    if (i < NN) { g_deg[i] = 0; g_cur[i] = 0; }
}

__global__ void count_kernel(const int* __restrict__ dst) {
    int e = blockIdx.x * blockDim.x + threadIdx.x;
    if (e < EE) atomicAdd(&g_deg[dst[e]], 1);
}

// single-block exclusive scan over g_deg -> g_off (n = NN)
__global__ void scan_kernel() {
    __shared__ int sh[1024];
    __shared__ int carry;
    if (threadIdx.x == 0) carry = 0;
    __syncthreads();
    for (int base = 0; base < NN; base += 1024) {
        int i = base + threadIdx.x;
        int v = (i < NN) ? g_deg[i] : 0;
        sh[threadIdx.x] = v;
        __syncthreads();
        // Hillis-Steele inclusive scan
        for (int ofs = 1; ofs < 1024; ofs <<= 1) {
            int t = (threadIdx.x >= ofs) ? sh[threadIdx.x - ofs] : 0;
            __syncthreads();
            sh[threadIdx.x] += t;
            __syncthreads();
        }
        if (i < NN) g_off[i] = carry + sh[threadIdx.x] - v;  // exclusive
        __syncthreads();
        if (threadIdx.x == 0) carry += sh[1023];
        __syncthreads();
    }
    if (threadIdx.x == 0) g_off[NN] = carry;
}

__global__ void fill_kernel(const int* __restrict__ src, const int* __restrict__ dst) {
    int e = blockIdx.x * blockDim.x + threadIdx.x;
    if (e < EE) {
        int d = dst[e];
        int pos = g_off[d] + atomicAdd(&g_cur[d], 1);
        g_csr[pos] = src[e];
    }
}

// ---------------- mean aggregation: warp per node ----------------
__global__ void agg_kernel(const float* __restrict__ h, float* __restrict__ neigh) {
    int gt = blockIdx.x * blockDim.x + threadIdx.x;
    int node = gt >> 5;
    int lane = gt & 31;
    if (node >= NN) return;
    int s = g_off[node];
    int e = g_off[node + 1];
    float ax = 0.f, ay = 0.f, az = 0.f, aw = 0.f;
    for (int j = s; j < e; j++) {
        int sidx = g_csr[j];
        float4 v = *reinterpret_cast<const float4*>(h + (size_t)sidx * DHID + lane * 4);
        ax += v.x; ay += v.y; az += v.z; aw += v.w;
    }
    int deg = e - s;
    float inv = 1.0f / (float)max(deg, 1);
    float4 o = make_float4(ax * inv, ay * inv, az * inv, aw * inv);
    *reinterpret_cast<float4*>(neigh + (size_t)node * DHID + lane * 4) = o;
}

// ---------------- fused SAGE GEMM:  out = act(h@Ws + neigh@Wn + b) ----------------
// concat-K GEMM: A = [h | neigh] (K=256), B = [Ws ; Wn] (256 x DOUT)
// block tile 64x64, 256 threads, 4x4 per thread, BK=16
template <int DOUT, bool RELU>
__global__ void sage_gemm_kernel(const float* __restrict__ h,
                                 const float* __restrict__ neigh,
                                 const float* __restrict__ Ws,
                                 const float* __restrict__ Wn,
                                 const float* __restrict__ bias,
                                 const float* __restrict__ mask,
                                 float* __restrict__ out) {
    const int BM = 64, BN = 64, BK = 16;
    __shared__ float As[BK][BM + 4];
    __shared__ float Bs[BK][BN];

    int bm = blockIdx.y * BM;
    int bn = blockIdx.x * BN;
    int tx = threadIdx.x % 16;   // col group
    int ty = threadIdx.x / 16;   // row group

    float acc[4][4];
#pragma unroll
    for (int i = 0; i < 4; i++)
#pragma unroll
        for (int j = 0; j < 4; j++) acc[i][j] = 0.f;

    // A-load mapping: 64 rows x 16 k, float4 per thread
    int a_row = threadIdx.x / 4;            // 0..63
    int a_kc  = (threadIdx.x % 4) * 4;      // 0,4,8,12
    // B-load mapping: 16 rows x 64 cols, float4 per thread
    int b_row = threadIdx.x / 16;           // 0..15
    int b_col = (threadIdx.x % 16) * 4;     // 0..60

    for (int k0 = 0; k0 < 256; k0 += BK) {
        const float* asrc = (k0 < 128) ? h : neigh;
        const float* wsrc = (k0 < 128) ? Ws : Wn;
        int klocal = (k0 & 127);

        int grow = bm + a_row;
        float4 av;
        if (grow < NN)
            av = *reinterpret_cast<const float4*>(asrc + (size_t)grow * DHID + klocal + a_kc);
        else
            av = make_float4(0.f, 0.f, 0.f, 0.f);
        As[a_kc + 0][a_row] = av.x;
        As[a_kc + 1][a_row] = av.y;
        As[a_kc + 2][a_row] = av.z;
        As[a_kc + 3][a_row] = av.w;

        float4 bv = *reinterpret_cast<const float4*>(wsrc + (size_t)(klocal + b_row) * DOUT + bn + b_col);
        Bs[b_row][b_col + 0] = bv.x;
        Bs[b_row][b_col + 1] = bv.y;
        Bs[b_row][b_col + 2] = bv.z;
        Bs[b_row][b_col + 3] = bv.w;

        __syncthreads();

#pragma unroll
        for (int kk = 0; kk < BK; kk++) {
            float a[4], bb[4];
#pragma unroll
            for (int i = 0; i < 4; i++) a[i] = As[kk][ty * 4 + i];
#pragma unroll
            for (int j = 0; j < 4; j++) bb[j] = Bs[kk][tx * 4 + j];
#pragma unroll
            for (int i = 0; i < 4; i++)
#pragma unroll
                for (int j = 0; j < 4; j++) acc[i][j] += a[i] * bb[j];
        }
        __syncthreads();
    }

#pragma unroll
    for (int i = 0; i < 4; i++) {
        int r = bm + ty * 4 + i;
        if (r >= NN) continue;
#pragma unroll
        for (int j = 0; j < 4; j++) {
            int c = bn + tx * 4 + j;
            float v = acc[i][j] + bias[c];
            if (RELU) {
                v = fmaxf(v, 0.f) * mask[(size_t)r * DOUT + c];
            }
            out[(size_t)r * DOUT + c] = v;
        }
    }
}

// ---------------- launch ----------------
extern "C" void kernel_launch(void* const* d_in, const int* in_sizes, int n_in,
                              void* d_out, int out_size) {
    const float* x   = (const float*)d_in[0];
    const int*   src = (const int*)d_in[1];
    const int*   dst = (const int*)d_in[2];
    const float* Ws1 = (const float*)d_in[3];
    const float* Wn1 = (const float*)d_in[4];
    const float* b1  = (const float*)d_in[5];
    const float* Ws2 = (const float*)d_in[6];
    const float* Wn2 = (const float*)d_in[7];
    const float* b2  = (const float*)d_in[8];
    const float* Ws3 = (const float*)d_in[9];
    const float* Wn3 = (const float*)d_in[10];
    const float* b3  = (const float*)d_in[11];
    const float* m1  = (const float*)d_in[12];
    const float* m2  = (const float*)d_in[13];
    float* out = (float*)d_out;

    // Real DEVICE addresses of the scratch symbols (host-side symbol names are
    // the host shadow copies — passing them to kernels is the ATS trap that
    // broke round 1).
    float *hA = nullptr, *hB = nullptr, *neigh = nullptr;
    cudaGetSymbolAddress((void**)&hA, g_hA);
    cudaGetSymbolAddress((void**)&hB, g_hB);
    cudaGetSymbolAddress((void**)&neigh, g_neigh);

    // ---- CSR build (idempotent per launch) ----
    zero_kernel<<<(NN + 255) / 256, 256>>>();
    count_kernel<<<(EE + 255) / 256, 256>>>(dst);
    scan_kernel<<<1, 1024>>>();
    fill_kernel<<<(EE + 255) / 256, 256>>>(src, dst);

    dim3 g128((DHID + 63) / 64, (NN + 63) / 64);
    dim3 g64((DOUT3 + 63) / 64, (NN + 63) / 64);
    int aggBlocks = (NN * 32 + 255) / 256;

    // ---- layer 1 ----
    agg_kernel<<<aggBlocks, 256>>>(x, neigh);
    sage_gemm_kernel<DHID, true><<<g128, 256>>>(x, neigh, Ws1, Wn1, b1, m1, hA);

    // ---- layer 2 ----
    agg_kernel<<<aggBlocks, 256>>>(hA, neigh);
    sage_gemm_kernel<DHID, true><<<g128, 256>>>(hA, neigh, Ws2, Wn2, b2, m2, hB);

    // ---- layer 3 ----
    agg_kernel<<<aggBlocks, 256>>>(hB, neigh);
    sage_gemm_kernel<DOUT3, false><<<g64, 256>>>(hB, neigh, Ws3, Wn3, b3, nullptr, out);
}

// round 4
// speedup vs baseline: 1.7999x; 1.7999x over previous
#include <cuda_runtime.h>
#include <cuda_bf16.h>
#include <cstdint>

// Problem constants
#define NN 50000
#define EE 800000
#define DHID 128
#define DOUT3 64

// ---------------- device scratch ----------------
__device__ float g_hA[NN * DHID];
__device__ float g_hB[NN * DHID];
__device__ float g_neigh[NN * DHID];
__device__ int   g_deg[NN];
__device__ int   g_off[NN + 1];
__device__ int   g_cur[NN];
__device__ int   g_csr[EE];

// ---------------- CSR build ----------------
__global__ void zero_kernel() {
    int i = blockIdx.x * blockDim.x + threadIdx.x;
    if (i < NN) { g_deg[i] = 0; g_cur[i] = 0; }
}
__global__ void count_kernel(const int* __restrict__ dst) {
    int e = blockIdx.x * blockDim.x + threadIdx.x;
    if (e < EE) atomicAdd(&g_deg[dst[e]], 1);
}
__global__ void scan_kernel() {
    __shared__ int sh[1024];
    __shared__ int carry;
    if (threadIdx.x == 0) carry = 0;
    __syncthreads();
    for (int base = 0; base < NN; base += 1024) {
        int i = base + threadIdx.x;
        int v = (i < NN) ? g_deg[i] : 0;
        sh[threadIdx.x] = v;
        __syncthreads();
        for (int ofs = 1; ofs < 1024; ofs <<= 1) {
            int t = (threadIdx.x >= ofs) ? sh[threadIdx.x - ofs] : 0;
            __syncthreads();
            sh[threadIdx.x] += t;
            __syncthreads();
        }
        if (i < NN) g_off[i] = carry + sh[threadIdx.x] - v;
        __syncthreads();
        if (threadIdx.x == 0) carry += sh[1023];
        __syncthreads();
    }
    if (threadIdx.x == 0) g_off[NN] = carry;
}
__global__ void fill_kernel(const int* __restrict__ src, const int* __restrict__ dst) {
    int e = blockIdx.x * blockDim.x + threadIdx.x;
    if (e < EE) {
        int d = dst[e];
        int pos = g_off[d] + atomicAdd(&g_cur[d], 1);
        g_csr[pos] = src[e];
    }
}

// ---------------- mean aggregation: warp per node ----------------
__global__ void agg_kernel(const float* __restrict__ h, float* __restrict__ neigh) {
    int gt = blockIdx.x * blockDim.x + threadIdx.x;
    int node = gt >> 5;
    int lane = gt & 31;
    if (node >= NN) return;
    int s = g_off[node];
    int e = g_off[node + 1];
    float ax = 0.f, ay = 0.f, az = 0.f, aw = 0.f;
    for (int j = s; j < e; j++) {
        int sidx = g_csr[j];
        float4 v = *reinterpret_cast<const float4*>(h + (size_t)sidx * DHID + lane * 4);
        ax += v.x; ay += v.y; az += v.z; aw += v.w;
    }
    int deg = e - s;
    float inv = 1.0f / (float)max(deg, 1);
    float4 o = make_float4(ax * inv, ay * inv, az * inv, aw * inv);
    *reinterpret_cast<float4*>(neigh + (size_t)node * DHID + lane * 4) = o;
}

// ---------------- bf16-split tensor-core GEMM (mma.sync, HMMA) ----------------
__device__ __forceinline__ void mma_bf16(float* d, const uint32_t* a, const uint32_t* b) {
    asm volatile(
        "mma.sync.aligned.m16n8k16.row.col.f32.bf16.bf16.f32 "
        "{%0,%1,%2,%3}, {%4,%5,%6,%7}, {%8,%9}, {%0,%1,%2,%3};"
        : "+f"(d[0]), "+f"(d[1]), "+f"(d[2]), "+f"(d[3])
        : "r"(a[0]), "r"(a[1]), "r"(a[2]), "r"(a[3]), "r"(b[0]), "r"(b[1]));
}
__device__ __forceinline__ uint32_t pack_bf16(float x, float y) {
    __nv_bfloat162 t = __floats2bfloat162_rn(x, y);
    return *reinterpret_cast<uint32_t*>(&t);
}

// out[M=128/CTA, DOUT] = act([h|neigh] @ [Ws;Wn] + b), K=256 over 8 chunks of 32.
// A,B split into bf16 hi/lo; acc += Ahi*Bhi + Ahi*Blo + Alo*Bhi (fp32).
// SMEM rows padded to 40 bf16 (80B) -> conflict-free 32-bit fragment loads.
template <int DOUT, bool RELU>
__global__ void __launch_bounds__(256, 1)
sage_mma_kernel(const float* __restrict__ h,
                const float* __restrict__ neigh,
                const float* __restrict__ Ws,
                const float* __restrict__ Wn,
                const float* __restrict__ bias,
                const float* __restrict__ mask,
                float* __restrict__ out) {
    constexpr int PAD = 40;             // row stride in bf16 elements
    constexpr int NHALF = DOUT / 2;     // cols per warp-column-group
    constexpr int NT = NHALF / 8;       // n8 tiles per warp (8 or 4)
    constexpr int NPAIR = DOUT * 16 / 256;  // B k-pairs per thread per chunk (8 or 4)

    __shared__ __align__(16) uint16_t sAh[128][PAD];
    __shared__ __align__(16) uint16_t sAl[128][PAD];
    __shared__ __align__(16) uint16_t sBh[DOUT][PAD];
    __shared__ __align__(16) uint16_t sBl[DOUT][PAD];

    const int tid = threadIdx.x;
    const int wid = tid >> 5;
    const int lane = tid & 31;
    const int g = lane >> 2;       // group row
    const int tg = lane & 3;       // thread-in-group
    const int bm = blockIdx.x * 128;

    // warp tiling: 4 warps down M (32 rows each), 2 warps across N (NHALF each)
    const int wm = (wid & 3) * 32;
    const int wn = (wid >> 2) * NHALF;

    float acc[2][NT][4];
#pragma unroll
    for (int m = 0; m < 2; m++)
#pragma unroll
        for (int n = 0; n < NT; n++)
#pragma unroll
            for (int i = 0; i < 4; i++) acc[m][n][i] = 0.f;

    // ---- prefetch registers ----
    float4 pa[4];
    float pb0[NPAIR], pb1[NPAIR];

    // A-load mapping: 1024 float4 per chunk, 4 per thread
    // f4idx = tid + i*256 -> row = f4idx/8 (0..127), c4 = f4idx%8 (k-quad)
    auto load_gmem = [&](int ch) {
        const int kbase = ch * 32;
        const float* asrc = (kbase < 128) ? h : neigh;
        const float* wsrc = (kbase < 128) ? Ws : Wn;
        const int klocal = kbase & 127;
#pragma unroll
        for (int i = 0; i < 4; i++) {
            int f4idx = tid + i * 256;
            int row = f4idx >> 3, c4 = f4idx & 7;
            int grow = bm + row;
            if (grow < NN)
                pa[i] = *reinterpret_cast<const float4*>(asrc + (size_t)grow * 128 + klocal + c4 * 4);
            else
                pa[i] = make_float4(0.f, 0.f, 0.f, 0.f);
        }
#pragma unroll
        for (int i = 0; i < NPAIR; i++) {
            int idx = tid + i * 256;
            int kp = idx / DOUT;          // 0..15
            int n = idx % DOUT;
            int k0 = klocal + kp * 2;
            pb0[i] = wsrc[(size_t)k0 * DOUT + n];
            pb1[i] = wsrc[(size_t)(k0 + 1) * DOUT + n];
        }
    };

    auto store_smem = [&]() {
#pragma unroll
        for (int i = 0; i < 4; i++) {
            int f4idx = tid + i * 256;
            int row = f4idx >> 3, c4 = f4idx & 7;
            float4 v = pa[i];
            __nv_bfloat16 hx = __float2bfloat16(v.x);
            __nv_bfloat16 hy = __float2bfloat16(v.y);
            __nv_bfloat16 hz = __float2bfloat16(v.z);
            __nv_bfloat16 hw = __float2bfloat16(v.w);
            uint32_t* ph = reinterpret_cast<uint32_t*>(&sAh[row][c4 * 4]);
            uint32_t* pl = reinterpret_cast<uint32_t*>(&sAl[row][c4 * 4]);
            ph[0] = pack_bf16(v.x, v.y);   // hi of x,y (pack_bf16 rounds; recompute residuals vs rounded)
            ph[1] = pack_bf16(v.z, v.w);
            pl[0] = pack_bf16(v.x - __bfloat162float(hx), v.y - __bfloat162float(hy));
            pl[1] = pack_bf16(v.z - __bfloat162float(hz), v.w - __bfloat162float(hw));
        }
#pragma unroll
        for (int i = 0; i < NPAIR; i++) {
            int idx = tid + i * 256;
            int kp = idx / DOUT;
            int n = idx % DOUT;
            __nv_bfloat16 h0 = __float2bfloat16(pb0[i]);
            __nv_bfloat16 h1 = __float2bfloat16(pb1[i]);
            *reinterpret_cast<uint32_t*>(&sBh[n][kp * 2]) = pack_bf16(pb0[i], pb1[i]);
            *reinterpret_cast<uint32_t*>(&sBl[n][kp * 2]) =
                pack_bf16(pb0[i] - __bfloat162float(h0), pb1[i] - __bfloat162float(h1));
        }
    };

    load_gmem(0);

    for (int ch = 0; ch < 8; ch++) {
        store_smem();
        __syncthreads();
        if (ch < 7) load_gmem(ch + 1);

        // compute on current chunk (k = 32 -> 2 k-steps of 16)
#pragma unroll
        for (int ks = 0; ks < 2; ks++) {
            uint32_t ah[2][4], al[2][4];
#pragma unroll
            for (int m = 0; m < 2; m++) {
                int r0 = wm + m * 16 + g;
                int kc = ks * 16 + tg * 2;
                ah[m][0] = *reinterpret_cast<const uint32_t*>(&sAh[r0][kc]);
                ah[m][1] = *reinterpret_cast<const uint32_t*>(&sAh[r0 + 8][kc]);
                ah[m][2] = *reinterpret_cast<const uint32_t*>(&sAh[r0][kc + 8]);
                ah[m][3] = *reinterpret_cast<const uint32_t*>(&sAh[r0 + 8][kc + 8]);
                al[m][0] = *reinterpret_cast<const uint32_t*>(&sAl[r0][kc]);
                al[m][1] = *reinterpret_cast<const uint32_t*>(&sAl[r0 + 8][kc]);
                al[m][2] = *reinterpret_cast<const uint32_t*>(&sAl[r0][kc + 8]);
                al[m][3] = *reinterpret_cast<const uint32_t*>(&sAl[r0 + 8][kc + 8]);
            }
#pragma unroll
            for (int nt = 0; nt < NT; nt++) {
                int nrow = wn + nt * 8 + g;
                int kc = ks * 16 + tg * 2;
                uint32_t bh[2], bl[2];
                bh[0] = *reinterpret_cast<const uint32_t*>(&sBh[nrow][kc]);
                bh[1] = *reinterpret_cast<const uint32_t*>(&sBh[nrow][kc + 8]);
                bl[0] = *reinterpret_cast<const uint32_t*>(&sBl[nrow][kc]);
                bl[1] = *reinterpret_cast<const uint32_t*>(&sBl[nrow][kc + 8]);
#pragma unroll
                for (int m = 0; m < 2; m++) {
                    mma_bf16(acc[m][nt], ah[m], bh);
                    mma_bf16(acc[m][nt], ah[m], bl);
                    mma_bf16(acc[m][nt], al[m], bh);
                }
            }
        }
        __syncthreads();
    }

    // ---- epilogue: bias + relu*mask, float2 stores ----
#pragma unroll
    for (int m = 0; m < 2; m++) {
        int r0 = bm + wm + m * 16 + g;
#pragma unroll
        for (int nt = 0; nt < NT; nt++) {
            int c = wn + nt * 8 + tg * 2;
            float bx = bias[c], by = bias[c + 1];
            // rows r0 and r0+8
            if (r0 < NN) {
                float v0 = acc[m][nt][0] + bx;
                float v1 = acc[m][nt][1] + by;
                if (RELU) {
                    float2 mv = *reinterpret_cast<const float2*>(mask + (size_t)r0 * DOUT + c);
                    v0 = fmaxf(v0, 0.f) * mv.x;
                    v1 = fmaxf(v1, 0.f) * mv.y;
                }
                *reinterpret_cast<float2*>(out + (size_t)r0 * DOUT + c) = make_float2(v0, v1);
            }
            int r1 = r0 + 8;
            if (r1 < NN) {
                float v0 = acc[m][nt][2] + bx;
                float v1 = acc[m][nt][3] + by;
                if (RELU) {
                    float2 mv = *reinterpret_cast<const float2*>(mask + (size_t)r1 * DOUT + c);
                    v0 = fmaxf(v0, 0.f) * mv.x;
                    v1 = fmaxf(v1, 0.f) * mv.y;
                }
                *reinterpret_cast<float2*>(out + (size_t)r1 * DOUT + c) = make_float2(v0, v1);
            }
        }
    }
}

// ---------------- launch ----------------
extern "C" void kernel_launch(void* const* d_in, const int* in_sizes, int n_in,
                              void* d_out, int out_size) {
    const float* x   = (const float*)d_in[0];
    const int*   src = (const int*)d_in[1];
    const int*   dst = (const int*)d_in[2];
    const float* Ws1 = (const float*)d_in[3];
    const float* Wn1 = (const float*)d_in[4];
    const float* b1  = (const float*)d_in[5];
    const float* Ws2 = (const float*)d_in[6];
    const float* Wn2 = (const float*)d_in[7];
    const float* b2  = (const float*)d_in[8];
    const float* Ws3 = (const float*)d_in[9];
    const float* Wn3 = (const float*)d_in[10];
    const float* b3  = (const float*)d_in[11];
    const float* m1  = (const float*)d_in[12];
    const float* m2  = (const float*)d_in[13];
    float* out = (float*)d_out;

    // Real DEVICE addresses (host symbol = ATS shadow trap, see R1)
    float *hA = nullptr, *hB = nullptr, *neigh = nullptr;
    cudaGetSymbolAddress((void**)&hA, g_hA);
    cudaGetSymbolAddress((void**)&hB, g_hB);
    cudaGetSymbolAddress((void**)&neigh, g_neigh);

    // ---- CSR build ----
    zero_kernel<<<(NN + 255) / 256, 256>>>();
    count_kernel<<<(EE + 255) / 256, 256>>>(dst);
    scan_kernel<<<1, 1024>>>();
    fill_kernel<<<(EE + 255) / 256, 256>>>(src, dst);

    int tiles = (NN + 127) / 128;   // 391
    int aggBlocks = (NN * 32 + 255) / 256;

    // ---- layer 1 ----
    agg_kernel<<<aggBlocks, 256>>>(x, neigh);
    sage_mma_kernel<DHID, true><<<tiles, 256>>>(x, neigh, Ws1, Wn1, b1, m1, hA);

    // ---- layer 2 ----
    agg_kernel<<<aggBlocks, 256>>>(hA, neigh);
    sage_mma_kernel<DHID, true><<<tiles, 256>>>(hA, neigh, Ws2, Wn2, b2, m2, hB);

    // ---- layer 3 ----
    agg_kernel<<<aggBlocks, 256>>>(hB, neigh);
    sage_mma_kernel<DOUT3, false><<<tiles, 256>>>(hB, neigh, Ws3, Wn3, b3, nullptr, out);
}

// round 6
// speedup vs baseline: 2.6286x; 1.4604x over previous
#include <cuda_runtime.h>
#include <cuda_bf16.h>
#include <cstdint>

#define NN 50000
#define EE 800000
#define NBLK 196   // ceil(NN/256)

// ---------------- device scratch ----------------
__device__ float g_hA[NN * 128];
__device__ float g_hB[NN * 128];
__device__ float g_neigh[NN * 128];   // layers 1-2: neigh; layer 3: [self+b | proj] tmp
__device__ int   g_deg[NN];
__device__ int   g_off[NN + 1];
__device__ int   g_cur[NN];
__device__ int   g_csr[EE];
__device__ int   g_bsum[256];
__device__ int   g_boff[256];
__device__ __nv_bfloat16 g_Bhi[3 * 128 * 256];
__device__ __nv_bfloat16 g_Blo[3 * 128 * 256];

// ---------------- helpers ----------------
__device__ __forceinline__ uint32_t smem_u32(const void* p) {
    uint32_t a;
    asm("{ .reg .u64 t; cvta.to.shared.u64 t, %1; cvt.u32.u64 %0, t; }" : "=r"(a) : "l"(p));
    return a;
}
__device__ __forceinline__ uint32_t pack_bf16(float x, float y) {
    __nv_bfloat162 t = __floats2bfloat162_rn(x, y);
    return *reinterpret_cast<uint32_t*>(&t);
}
__device__ __forceinline__ void mma_bf16(float* d, const uint32_t* a, const uint32_t* b) {
    asm volatile(
        "mma.sync.aligned.m16n8k16.row.col.f32.bf16.bf16.f32 "
        "{%0,%1,%2,%3}, {%4,%5,%6,%7}, {%8,%9}, {%0,%1,%2,%3};"
        : "+f"(d[0]), "+f"(d[1]), "+f"(d[2]), "+f"(d[3])
        : "r"(a[0]), "r"(a[1]), "r"(a[2]), "r"(a[3]), "r"(b[0]), "r"(b[1]));
}
__device__ __forceinline__ void ldsm_x4(uint32_t* r, uint32_t addr) {
    asm volatile("ldmatrix.sync.aligned.m8n8.x4.shared.b16 {%0,%1,%2,%3}, [%4];"
                 : "=r"(r[0]), "=r"(r[1]), "=r"(r[2]), "=r"(r[3]) : "r"(addr));
}

// ---------------- B preparation: W (fp32) -> transposed bf16 hi/lo ----------------
// mode 0: B[k][n], k<128 -> W1[k*128+n], k>=128 -> W2[(k-128)*128+n]; K=256 (layers 1-2)
// mode 1: B[k][n], n<64 -> W1[k*64+n], n>=64 -> W2[k*64+n-64];       K=128 (layer 3)
__global__ void prep_B_kernel(const float* __restrict__ W1, const float* __restrict__ W2,
                              __nv_bfloat16* __restrict__ bhi, __nv_bfloat16* __restrict__ blo,
                              int mode) {
    int K = (mode == 0) ? 256 : 128;
    int idx = blockIdx.x * blockDim.x + threadIdx.x;
    if (idx >= 128 * K) return;
    int n = idx / K, k = idx % K;
    float w;
    if (mode == 0) w = (k < 128) ? W1[k * 128 + n] : W2[(k - 128) * 128 + n];
    else           w = (n < 64) ? W1[k * 64 + n] : W2[k * 64 + (n - 64)];
    __nv_bfloat16 hi = __float2bfloat16(w);
    bhi[idx] = hi;
    blo[idx] = __float2bfloat16(w - __bfloat162float(hi));
}

// ---------------- CSR build ----------------
__global__ void zero_kernel() {
    int i = blockIdx.x * blockDim.x + threadIdx.x;
    if (i < NN) { g_deg[i] = 0; g_cur[i] = 0; }
}
__global__ void count_kernel(const int* __restrict__ dst) {
    int e = blockIdx.x * blockDim.x + threadIdx.x;
    if (e < EE) atomicAdd(&g_deg[dst[e]], 1);
}
__global__ void scan_partials() {
    __shared__ int sh[256];
    int t = threadIdx.x;
    int i = blockIdx.x * 256 + t;
    sh[t] = (i < NN) ? g_deg[i] : 0;
    __syncthreads();
    for (int o = 128; o > 0; o >>= 1) {
        if (t < o) sh[t] += sh[t + o];
        __syncthreads();
    }
    if (t == 0) g_bsum[blockIdx.x] = sh[0];
}
__global__ void scan_bsums() {
    __shared__ int sh[256];
    int t = threadIdx.x;
    int v = (t < NBLK) ? g_bsum[t] : 0;
    sh[t] = v;
    __syncthreads();
    for (int o = 1; o < 256; o <<= 1) {
        int x = (t >= o) ? sh[t - o] : 0;
        __syncthreads();
        sh[t] += x;
        __syncthreads();
    }
    if (t < NBLK) g_boff[t] = sh[t] - v;   // exclusive
}
__global__ void scan_final() {
    __shared__ int sh[256];
    int t = threadIdx.x;
    int i = blockIdx.x * 256 + t;
    int v = (i < NN) ? g_deg[i] : 0;
    sh[t] = v;
    __syncthreads();
    for (int o = 1; o < 256; o <<= 1) {
        int x = (t >= o) ? sh[t - o] : 0;
        __syncthreads();
        sh[t] += x;
        __syncthreads();
    }
    if (i <= NN) g_off[i] = g_boff[blockIdx.x] + sh[t] - v;  // exclusive; g_off[NN]=EE
}
__global__ void fill_kernel(const int* __restrict__ src, const int* __restrict__ dst) {
    int e = blockIdx.x * blockDim.x + threadIdx.x;
    if (e < EE) {
        int d = dst[e];
        int pos = g_off[d] + atomicAdd(&g_cur[d], 1);
        g_csr[pos] = src[e];
    }
}

// ---------------- mean aggregation (128-dim): warp per node ----------------
__global__ void agg_kernel(const float* __restrict__ h, float* __restrict__ neigh) {
    int gt = blockIdx.x * blockDim.x + threadIdx.x;
    int node = gt >> 5;
    int lane = gt & 31;
    if (node >= NN) return;
    int s = g_off[node], e = g_off[node + 1];
    float ax = 0.f, ay = 0.f, az = 0.f, aw = 0.f;
    for (int j = s; j < e; j++) {
        int sidx = g_csr[j];
        float4 v = *reinterpret_cast<const float4*>(h + (size_t)sidx * 128 + lane * 4);
        ax += v.x; ay += v.y; az += v.z; aw += v.w;
    }
    float inv = 1.0f / (float)max(e - s, 1);
    *reinterpret_cast<float4*>(neigh + (size_t)node * 128 + lane * 4) =
        make_float4(ax * inv, ay * inv, az * inv, aw * inv);
}

// ---------------- layer-3 final: out = self + mean(proj[src]) ----------------
// tmp[n][0:64) = h@Ws3 + b3 ; tmp[n][64:128) = h@Wn3
__global__ void agg3_kernel(const float* __restrict__ tmp, float* __restrict__ out) {
    int gt = blockIdx.x * blockDim.x + threadIdx.x;
    int node = gt >> 5;
    int lane = gt & 31;
    if (node >= NN) return;
    int s = g_off[node], e = g_off[node + 1];
    float ax = 0.f, ay = 0.f;
    for (int j = s; j < e; j++) {
        int sidx = g_csr[j];
        float2 v = *reinterpret_cast<const float2*>(tmp + (size_t)sidx * 128 + 64 + lane * 2);
        ax += v.x; ay += v.y;
    }
    float inv = 1.0f / (float)max(e - s, 1);
    float2 self = *reinterpret_cast<const float2*>(tmp + (size_t)node * 128 + lane * 2);
    *reinterpret_cast<float2*>(out + (size_t)node * 64 + lane * 2) =
        make_float2(self.x + ax * inv, self.y + ay * inv);
}

// ---------------- bf16-split tensor-core GEMM, ldmatrix + double buffer ----------------
// out[M=128/CTA, 128] = act( A @ B + bias ), A = [A0|A1] (DUAL) or A0, K = KCHUNKS*32
// acc = Ahi*Bhi + Ahi*Blo + Alo*Bhi (fp32), B pre-split in gmem bf16.
template <int KCHUNKS, bool DUAL, bool RELU, bool BIAS64>
__global__ void __launch_bounds__(256, 2)
sage_mma_kernel(const float* __restrict__ A0, const float* __restrict__ A1,
                const __nv_bfloat16* __restrict__ Bhi, const __nv_bfloat16* __restrict__ Blo,
                const float* __restrict__ bias, const float* __restrict__ mask,
                float* __restrict__ out) {
    constexpr int PAD = 40;                 // halves per smem row (80B stride: conflict-free ldmatrix)
    constexpr int KTOT = KCHUNKS * 32;
    constexpr int BUFH = 128 * PAD;         // halves per buffer
    extern __shared__ uint16_t sm[];
    uint16_t* sAh = sm;                     // [2][128][PAD]
    uint16_t* sAl = sm + 2 * BUFH;
    uint16_t* sBh = sm + 4 * BUFH;
    uint16_t* sBl = sm + 6 * BUFH;
    const uint32_t base = smem_u32(sm);

    const int tid = threadIdx.x, lane = tid & 31, wid = tid >> 5;
    const int bm = blockIdx.x * 128;
    const int wm = (wid & 3) * 32;          // 4 warps down M
    const int wn = (wid >> 2) * 64;         // 2 warps across N

    float acc[2][8][4];
#pragma unroll
    for (int m = 0; m < 2; m++)
#pragma unroll
        for (int n = 0; n < 8; n++)
#pragma unroll
            for (int i = 0; i < 4; i++) acc[m][n][i] = 0.f;

    float4 pa[4];
    auto loadA = [&](int ch) {
        const float* asrc = DUAL ? (ch < KCHUNKS / 2 ? A0 : A1) : A0;
        int klocal = DUAL ? (ch & (KCHUNKS / 2 - 1)) * 32 : ch * 32;
#pragma unroll
        for (int i = 0; i < 4; i++) {
            int row = (tid >> 3) + i * 32;
            int grow = bm + row;
            pa[i] = (grow < NN)
                ? *reinterpret_cast<const float4*>(asrc + (size_t)grow * 128 + klocal + (tid & 7) * 4)
                : make_float4(0.f, 0.f, 0.f, 0.f);
        }
    };
    auto storeA = [&](int buf) {
#pragma unroll
        for (int i = 0; i < 4; i++) {
            int row = (tid >> 3) + i * 32;
            float4 v = pa[i];
            __nv_bfloat16 hx = __float2bfloat16(v.x);
            __nv_bfloat16 hy = __float2bfloat16(v.y);
            __nv_bfloat16 hz = __float2bfloat16(v.z);
            __nv_bfloat16 hw = __float2bfloat16(v.w);
            uint32_t h01 = pack_bf16(v.x, v.y);
            uint32_t h23 = pack_bf16(v.z, v.w);
            uint32_t l01 = pack_bf16(v.x - __bfloat162float(hx), v.y - __bfloat162float(hy));
            uint32_t l23 = pack_bf16(v.z - __bfloat162float(hz), v.w - __bfloat162float(hw));
            int off = buf * BUFH + row * PAD + (tid & 7) * 4;
            *reinterpret_cast<uint2*>(&sAh[off]) = make_uint2(h01, h23);
            *reinterpret_cast<uint2*>(&sAl[off]) = make_uint2(l01, l23);
        }
    };
    auto stageB = [&](int ch, int buf) {
        int k0 = ch * 32;
#pragma unroll
        for (int j = 0; j < 2; j++) {
            int item = tid + j * 256;
            int n = item >> 2, q = item & 3;
            int soff = n * KTOT + k0 + q * 8;
            uint4 vh = *reinterpret_cast<const uint4*>(Bhi + soff);
            uint4 vl = *reinterpret_cast<const uint4*>(Blo + soff);
            int doff = buf * BUFH + n * PAD + q * 8;
            *reinterpret_cast<uint4*>(&sBh[doff]) = vh;
            *reinterpret_cast<uint4*>(&sBl[doff]) = vl;
        }
    };

    loadA(0);
    storeA(0);
    stageB(0, 0);

    for (int ch = 0; ch < KCHUNKS; ch++) {
        __syncthreads();
        int buf = ch & 1;
        bool more = (ch + 1 < KCHUNKS);
        if (more) loadA(ch + 1);   // issue LDGs early; latency hidden by MMA work

#pragma unroll
        for (int ks = 0; ks < 2; ks++) {
            uint32_t ah[2][4], al[2][4];
            int arow = wm + (lane & 7) + ((lane >> 3) & 1) * 8;
            int acol = ks * 16 + (lane >> 4) * 8;
#pragma unroll
            for (int m = 0; m < 2; m++) {
                uint32_t aoff = (uint32_t)(buf * BUFH + (arow + m * 16) * PAD + acol) * 2;
                ldsm_x4(ah[m], base + aoff);
                ldsm_x4(al[m], base + (uint32_t)(2 * BUFH) * 2 + aoff);
            }
            int brow = wn + (lane & 7) + ((lane >> 4) & 1) * 8;
            int bcol = ks * 16 + ((lane >> 3) & 1) * 8;
#pragma unroll
            for (int nt2 = 0; nt2 < 4; nt2++) {
                uint32_t bh[4], bl4[4];
                uint32_t boff = (uint32_t)(buf * BUFH + (brow + nt2 * 16) * PAD + bcol) * 2;
                ldsm_x4(bh, base + (uint32_t)(4 * BUFH) * 2 + boff);
                ldsm_x4(bl4, base + (uint32_t)(6 * BUFH) * 2 + boff);
#pragma unroll
                for (int m = 0; m < 2; m++) {
                    mma_bf16(acc[m][nt2 * 2], ah[m], &bh[0]);
                    mma_bf16(acc[m][nt2 * 2], ah[m], &bl4[0]);
                    mma_bf16(acc[m][nt2 * 2], al[m], &bh[0]);
                    mma_bf16(acc[m][nt2 * 2 + 1], ah[m], &bh[2]);
                    mma_bf16(acc[m][nt2 * 2 + 1], ah[m], &bl4[2]);
                    mma_bf16(acc[m][nt2 * 2 + 1], al[m], &bh[2]);
                }
            }
        }
        if (more) { storeA(buf ^ 1); stageB(ch + 1, buf ^ 1); }
    }

    // ---- epilogue ----
#pragma unroll
    for (int m = 0; m < 2; m++) {
        int r0 = bm + wm + m * 16 + (lane >> 2);
#pragma unroll
        for (int nt = 0; nt < 8; nt++) {
            int c = wn + nt * 8 + (lane & 3) * 2;
            float b0 = 0.f, b1 = 0.f;
            if (!BIAS64 || c < 64) { b0 = bias[c]; b1 = bias[c + 1]; }
            if (r0 < NN) {
                float v0 = acc[m][nt][0] + b0, v1 = acc[m][nt][1] + b1;
                if (RELU) {
                    float2 mv = *reinterpret_cast<const float2*>(mask + (size_t)r0 * 128 + c);
                    v0 = fmaxf(v0, 0.f) * mv.x;
                    v1 = fmaxf(v1, 0.f) * mv.y;
                }
                *reinterpret_cast<float2*>(out + (size_t)r0 * 128 + c) = make_float2(v0, v1);
            }
            int r1 = r0 + 8;
            if (r1 < NN) {
                float v0 = acc[m][nt][2] + b0, v1 = acc[m][nt][3] + b1;
                if (RELU) {
                    float2 mv = *reinterpret_cast<const float2*>(mask + (size_t)r1 * 128 + c);
                    v0 = fmaxf(v0, 0.f) * mv.x;
                    v1 = fmaxf(v1, 0.f) * mv.y;
                }
                *reinterpret_cast<float2*>(out + (size_t)r1 * 128 + c) = make_float2(v0, v1);
            }
        }
    }
}

// ---------------- launch ----------------
extern "C" void kernel_launch(void* const* d_in, const int* in_sizes, int n_in,
                              void* d_out, int out_size) {
    const float* x   = (const float*)d_in[0];
    const int*   src = (const int*)d_in[1];
    const int*   dst = (const int*)d_in[2];
    const float* Ws1 = (const float*)d_in[3];
    const float* Wn1 = (const float*)d_in[4];
    const float* b1  = (const float*)d_in[5];
    const float* Ws2 = (const float*)d_in[6];
    const float* Wn2 = (const float*)d_in[7];
    const float* b2  = (const float*)d_in[8];
    const float* Ws3 = (const float*)d_in[9];
    const float* Wn3 = (const float*)d_in[10];
    const float* b3  = (const float*)d_in[11];
    const float* m1  = (const float*)d_in[12];
    const float* m2  = (const float*)d_in[13];
    float* out = (float*)d_out;

    // Real DEVICE addresses (host symbol = ATS shadow trap, see R1)
    float *hA = nullptr, *hB = nullptr, *neigh = nullptr;
    __nv_bfloat16 *Bhi = nullptr, *Blo = nullptr;
    cudaGetSymbolAddress((void**)&hA, g_hA);
    cudaGetSymbolAddress((void**)&hB, g_hB);
    cudaGetSymbolAddress((void**)&neigh, g_neigh);
    cudaGetSymbolAddress((void**)&Bhi, g_Bhi);
    cudaGetSymbolAddress((void**)&Blo, g_Blo);

    constexpr int SMEM_GEMM = 8 * 128 * 40 * 2;  // 81920 B
    cudaFuncSetAttribute(sage_mma_kernel<8, true, true, false>,
                         cudaFuncAttributeMaxDynamicSharedMemorySize, SMEM_GEMM);
    cudaFuncSetAttribute(sage_mma_kernel<4, false, false, true>,
                         cudaFuncAttributeMaxDynamicSharedMemorySize, SMEM_GEMM);

    // ---- weight prep (bf16 hi/lo, transposed) ----
    prep_B_kernel<<<(128 * 256 + 255) / 256, 256>>>(Ws1, Wn1, Bhi, Blo, 0);
    prep_B_kernel<<<(128 * 256 + 255) / 256, 256>>>(Ws2, Wn2, Bhi + 32768, Blo + 32768, 0);
    prep_B_kernel<<<(128 * 128 + 255) / 256, 256>>>(Ws3, Wn3, Bhi + 65536, Blo + 65536, 1);

    // ---- CSR build ----
    zero_kernel<<<(NN + 255) / 256, 256>>>();
    count_kernel<<<(EE + 255) / 256, 256>>>(dst);
    scan_partials<<<NBLK, 256>>>();
    scan_bsums<<<1, 256>>>();
    scan_final<<<NBLK, 256>>>();
    fill_kernel<<<(EE + 255) / 256, 256>>>(src, dst);

    int tiles = (NN + 127) / 128;            // 391
    int aggBlocks = (NN * 32 + 255) / 256;

    // ---- layer 1 ----
    agg_kernel<<<aggBlocks, 256>>>(x, neigh);
    sage_mma_kernel<8, true, true, false><<<tiles, 256, SMEM_GEMM>>>(x, neigh, Bhi, Blo, b1, m1, hA);

    // ---- layer 2 ----
    agg_kernel<<<aggBlocks, 256>>>(hA, neigh);
    sage_mma_kernel<8, true, true, false><<<tiles, 256, SMEM_GEMM>>>(hA, neigh, Bhi + 32768, Blo + 32768, b2, m2, hB);

    // ---- layer 3: project first (tmp = [h@Ws3+b3 | h@Wn3]), then aggregate 64-dim ----
    sage_mma_kernel<4, false, false, true><<<tiles, 256, SMEM_GEMM>>>(hB, nullptr, Bhi + 65536, Blo + 65536, b3, nullptr, neigh);
    agg3_kernel<<<aggBlocks, 256>>>(neigh, out);
}

// round 7
// speedup vs baseline: 2.6321x; 1.0014x over previous
#include <cuda_runtime.h>
#include <cuda_bf16.h>
#include <cuda_fp16.h>
#include <cstdint>

#define NN 50000
#define EE 800000
#define NBLK 196   // ceil(NN/256)

// ---------------- device scratch ----------------
__device__ float g_hA[NN * 128];      // layer-1 out; reused as layer-3 self[NN*64]
__device__ float g_hB[NN * 128];      // layer-2 out
__device__ float g_neigh[NN * 128];   // aggregated neighbor features (fp32)
__device__ __half g_h16[NN * 128];    // fp16 gather mirror: x16 -> hA16 -> p16 (reused)
__device__ int   g_deg[NN];
__device__ int   g_off[NN + 1];
__device__ int   g_cur[NN];
__device__ int   g_csr[EE];
__device__ int   g_bsum[256];
__device__ int   g_boff[256];
__device__ __nv_bfloat16 g_Bhi[3 * 128 * 256];
__device__ __nv_bfloat16 g_Blo[3 * 128 * 256];

// ---------------- helpers ----------------
__device__ __forceinline__ uint32_t smem_u32(const void* p) {
    uint32_t a;
    asm("{ .reg .u64 t; cvta.to.shared.u64 t, %1; cvt.u32.u64 %0, t; }" : "=r"(a) : "l"(p));
    return a;
}
__device__ __forceinline__ uint32_t pack_bf16(float x, float y) {
    __nv_bfloat162 t = __floats2bfloat162_rn(x, y);
    return *reinterpret_cast<uint32_t*>(&t);
}
__device__ __forceinline__ void mma_bf16(float* d, const uint32_t* a, const uint32_t* b) {
    asm volatile(
        "mma.sync.aligned.m16n8k16.row.col.f32.bf16.bf16.f32 "
        "{%0,%1,%2,%3}, {%4,%5,%6,%7}, {%8,%9}, {%0,%1,%2,%3};"
        : "+f"(d[0]), "+f"(d[1]), "+f"(d[2]), "+f"(d[3])
        : "r"(a[0]), "r"(a[1]), "r"(a[2]), "r"(a[3]), "r"(b[0]), "r"(b[1]));
}
__device__ __forceinline__ void ldsm_x4(uint32_t* r, uint32_t addr) {
    asm volatile("ldmatrix.sync.aligned.m8n8.x4.shared.b16 {%0,%1,%2,%3}, [%4];"
                 : "=r"(r[0]), "=r"(r[1]), "=r"(r[2]), "=r"(r[3]) : "r"(addr));
}

// ---------------- B preparation: W (fp32) -> transposed bf16 hi/lo ----------------
__global__ void prep_B_kernel(const float* __restrict__ W1, const float* __restrict__ W2,
                              __nv_bfloat16* __restrict__ bhi, __nv_bfloat16* __restrict__ blo,
                              int mode) {
    int K = (mode == 0) ? 256 : 128;
    int idx = blockIdx.x * blockDim.x + threadIdx.x;
    if (idx >= 128 * K) return;
    int n = idx / K, k = idx % K;
    float w;
    if (mode == 0) w = (k < 128) ? W1[k * 128 + n] : W2[(k - 128) * 128 + n];
    else           w = (n < 64) ? W1[k * 64 + n] : W2[k * 64 + (n - 64)];
    __nv_bfloat16 hi = __float2bfloat16(w);
    bhi[idx] = hi;
    blo[idx] = __float2bfloat16(w - __bfloat162float(hi));
}

// ---------------- fp32 -> fp16 convert (for x) ----------------
__global__ void conv16_kernel(const float* __restrict__ src, __half* __restrict__ dst, int n2) {
    int i = blockIdx.x * blockDim.x + threadIdx.x;
    if (i < n2) {
        float2 v = *reinterpret_cast<const float2*>(src + (size_t)i * 2);
        *reinterpret_cast<__half2*>(dst + (size_t)i * 2) = __floats2half2_rn(v.x, v.y);
    }
}

// ---------------- CSR build ----------------
__global__ void zero_kernel() {
    int i = blockIdx.x * blockDim.x + threadIdx.x;
    if (i < NN) { g_deg[i] = 0; g_cur[i] = 0; }
}
__global__ void count_kernel(const int* __restrict__ dst) {
    int e = blockIdx.x * blockDim.x + threadIdx.x;
    if (e < EE) atomicAdd(&g_deg[dst[e]], 1);
}
__global__ void scan_partials() {
    __shared__ int sh[256];
    int t = threadIdx.x;
    int i = blockIdx.x * 256 + t;
    sh[t] = (i < NN) ? g_deg[i] : 0;
    __syncthreads();
    for (int o = 128; o > 0; o >>= 1) {
        if (t < o) sh[t] += sh[t + o];
        __syncthreads();
    }
    if (t == 0) g_bsum[blockIdx.x] = sh[0];
}
__global__ void scan_bsums() {
    __shared__ int sh[256];
    int t = threadIdx.x;
    int v = (t < NBLK) ? g_bsum[t] : 0;
    sh[t] = v;
    __syncthreads();
    for (int o = 1; o < 256; o <<= 1) {
        int x = (t >= o) ? sh[t - o] : 0;
        __syncthreads();
        sh[t] += x;
        __syncthreads();
    }
    if (t < NBLK) g_boff[t] = sh[t] - v;   // exclusive
}
__global__ void scan_final() {
    __shared__ int sh[256];
    int t = threadIdx.x;
    int i = blockIdx.x * 256 + t;
    int v = (i < NN) ? g_deg[i] : 0;
    sh[t] = v;
    __syncthreads();
    for (int o = 1; o < 256; o <<= 1) {
        int x = (t >= o) ? sh[t - o] : 0;
        __syncthreads();
        sh[t] += x;
        __syncthreads();
    }
    if (i <= NN) g_off[i] = g_boff[blockIdx.x] + sh[t] - v;  // exclusive; g_off[NN]=EE
}
__global__ void fill_kernel(const int* __restrict__ src, const int* __restrict__ dst) {
    int e = blockIdx.x * blockDim.x + threadIdx.x;
    if (e < EE) {
        int d = dst[e];
        int pos = g_off[d] + atomicAdd(&g_cur[d], 1);
        g_csr[pos] = src[e];
    }
}

// ---------------- mean aggregation from fp16 mirror (128-dim): warp per node ----------------
__global__ void agg_h16_kernel(const __half* __restrict__ h16, float* __restrict__ neigh) {
    int gt = blockIdx.x * blockDim.x + threadIdx.x;
    int node = gt >> 5;
    int lane = gt & 31;
    if (node >= NN) return;
    int s = g_off[node], e = g_off[node + 1];
    float a0 = 0.f, a1 = 0.f, a2 = 0.f, a3 = 0.f;
    for (int j = s; j < e; j++) {
        int sidx = g_csr[j];
        uint2 v = *reinterpret_cast<const uint2*>(h16 + (size_t)sidx * 128 + lane * 4);
        float2 f0 = __half22float2(*reinterpret_cast<__half2*>(&v.x));
        float2 f1 = __half22float2(*reinterpret_cast<__half2*>(&v.y));
        a0 += f0.x; a1 += f0.y; a2 += f1.x; a3 += f1.y;
    }
    float inv = 1.0f / (float)max(e - s, 1);
    *reinterpret_cast<float4*>(neigh + (size_t)node * 128 + lane * 4) =
        make_float4(a0 * inv, a1 * inv, a2 * inv, a3 * inv);
}

// ---------------- layer-3 final: out = self + mean(proj16[src]) ----------------
__global__ void agg3_h16_kernel(const __half* __restrict__ p16, const float* __restrict__ self,
                                float* __restrict__ out) {
    int gt = blockIdx.x * blockDim.x + threadIdx.x;
    int node = gt >> 5;
    int lane = gt & 31;
    if (node >= NN) return;
    int s = g_off[node], e = g_off[node + 1];
    float a0 = 0.f, a1 = 0.f;
    for (int j = s; j < e; j++) {
        int sidx = g_csr[j];
        uint32_t v = *reinterpret_cast<const uint32_t*>(p16 + (size_t)sidx * 64 + lane * 2);
        float2 f = __half22float2(*reinterpret_cast<__half2*>(&v));
        a0 += f.x; a1 += f.y;
    }
    float inv = 1.0f / (float)max(e - s, 1);
    float2 sv = *reinterpret_cast<const float2*>(self + (size_t)node * 64 + lane * 2);
    *reinterpret_cast<float2*>(out + (size_t)node * 64 + lane * 2) =
        make_float2(sv.x + a0 * inv, sv.y + a1 * inv);
}

// ---------------- bf16-split tensor-core GEMM, ldmatrix + double buffer ----------------
// MODE 0: relu*mask, out fp32 128-wide + h16 fp16 mirror (layer 1)
// MODE 1: relu*mask, out fp32 128-wide                      (layer 2)
// MODE 2: layer 3 split: cols<64 -> self fp32 (+bias), cols>=64 -> p16 fp16 (no bias)
template <int KCHUNKS, bool DUAL, int MODE>
__global__ void __launch_bounds__(256, 2)
sage_mma_kernel(const float* __restrict__ A0, const float* __restrict__ A1,
                const __nv_bfloat16* __restrict__ Bhi, const __nv_bfloat16* __restrict__ Blo,
                const float* __restrict__ bias, const float* __restrict__ mask,
                float* __restrict__ out, __half* __restrict__ h16out) {
    constexpr int PAD = 40;
    constexpr int KTOT = KCHUNKS * 32;
    constexpr int BUFH = 128 * PAD;
    extern __shared__ uint16_t sm[];
    uint16_t* sAh = sm;
    uint16_t* sAl = sm + 2 * BUFH;
    uint16_t* sBh = sm + 4 * BUFH;
    uint16_t* sBl = sm + 6 * BUFH;
    const uint32_t base = smem_u32(sm);

    const int tid = threadIdx.x, lane = tid & 31, wid = tid >> 5;
    const int bm = blockIdx.x * 128;
    const int wm = (wid & 3) * 32;
    const int wn = (wid >> 2) * 64;

    float acc[2][8][4];
#pragma unroll
    for (int m = 0; m < 2; m++)
#pragma unroll
        for (int n = 0; n < 8; n++)
#pragma unroll
            for (int i = 0; i < 4; i++) acc[m][n][i] = 0.f;

    float4 pa[4];
    auto loadA = [&](int ch) {
        const float* asrc = DUAL ? (ch < KCHUNKS / 2 ? A0 : A1) : A0;
        int klocal = DUAL ? (ch & (KCHUNKS / 2 - 1)) * 32 : ch * 32;
#pragma unroll
        for (int i = 0; i < 4; i++) {
            int row = (tid >> 3) + i * 32;
            int grow = bm + row;
            pa[i] = (grow < NN)
                ? *reinterpret_cast<const float4*>(asrc + (size_t)grow * 128 + klocal + (tid & 7) * 4)
                : make_float4(0.f, 0.f, 0.f, 0.f);
        }
    };
    auto storeA = [&](int buf) {
#pragma unroll
        for (int i = 0; i < 4; i++) {
            int row = (tid >> 3) + i * 32;
            float4 v = pa[i];
            __nv_bfloat16 hx = __float2bfloat16(v.x);
            __nv_bfloat16 hy = __float2bfloat16(v.y);
            __nv_bfloat16 hz = __float2bfloat16(v.z);
            __nv_bfloat16 hw = __float2bfloat16(v.w);
            uint32_t h01 = pack_bf16(v.x, v.y);
            uint32_t h23 = pack_bf16(v.z, v.w);
            uint32_t l01 = pack_bf16(v.x - __bfloat162float(hx), v.y - __bfloat162float(hy));
            uint32_t l23 = pack_bf16(v.z - __bfloat162float(hz), v.w - __bfloat162float(hw));
            int off = buf * BUFH + row * PAD + (tid & 7) * 4;
            *reinterpret_cast<uint2*>(&sAh[off]) = make_uint2(h01, h23);
            *reinterpret_cast<uint2*>(&sAl[off]) = make_uint2(l01, l23);
        }
    };
    auto stageB = [&](int ch, int buf) {
        int k0 = ch * 32;
#pragma unroll
        for (int j = 0; j < 2; j++) {
            int item = tid + j * 256;
            int n = item >> 2, q = item & 3;
            int soff = n * KTOT + k0 + q * 8;
            uint4 vh = *reinterpret_cast<const uint4*>(Bhi + soff);
            uint4 vl = *reinterpret_cast<const uint4*>(Blo + soff);
            int doff = buf * BUFH + n * PAD + q * 8;
            *reinterpret_cast<uint4*>(&sBh[doff]) = vh;
            *reinterpret_cast<uint4*>(&sBl[doff]) = vl;
        }
    };

    loadA(0);
    storeA(0);
    stageB(0, 0);

    for (int ch = 0; ch < KCHUNKS; ch++) {
        __syncthreads();
        int buf = ch & 1;
        bool more = (ch + 1 < KCHUNKS);
        if (more) loadA(ch + 1);

#pragma unroll
        for (int ks = 0; ks < 2; ks++) {
            uint32_t ah[2][4], al[2][4];
            int arow = wm + (lane & 7) + ((lane >> 3) & 1) * 8;
            int acol = ks * 16 + (lane >> 4) * 8;
#pragma unroll
            for (int m = 0; m < 2; m++) {
                uint32_t aoff = (uint32_t)(buf * BUFH + (arow + m * 16) * PAD + acol) * 2;
                ldsm_x4(ah[m], base + aoff);
                ldsm_x4(al[m], base + (uint32_t)(2 * BUFH) * 2 + aoff);
            }
            int brow = wn + (lane & 7) + ((lane >> 4) & 1) * 8;
            int bcol = ks * 16 + ((lane >> 3) & 1) * 8;
#pragma unroll
            for (int nt2 = 0; nt2 < 4; nt2++) {
                uint32_t bh[4], bl4[4];
                uint32_t boff = (uint32_t)(buf * BUFH + (brow + nt2 * 16) * PAD + bcol) * 2;
                ldsm_x4(bh, base + (uint32_t)(4 * BUFH) * 2 + boff);
                ldsm_x4(bl4, base + (uint32_t)(6 * BUFH) * 2 + boff);
#pragma unroll
                for (int m = 0; m < 2; m++) {
                    mma_bf16(acc[m][nt2 * 2], ah[m], &bh[0]);
                    mma_bf16(acc[m][nt2 * 2], ah[m], &bl4[0]);
                    mma_bf16(acc[m][nt2 * 2], al[m], &bh[0]);
                    mma_bf16(acc[m][nt2 * 2 + 1], ah[m], &bh[2]);
                    mma_bf16(acc[m][nt2 * 2 + 1], ah[m], &bl4[2]);
                    mma_bf16(acc[m][nt2 * 2 + 1], al[m], &bh[2]);
                }
            }
        }
        if (more) { storeA(buf ^ 1); stageB(ch + 1, buf ^ 1); }
    }

    // ---- epilogue ----
#pragma unroll
    for (int m = 0; m < 2; m++) {
        int r0 = bm + wm + m * 16 + (lane >> 2);
#pragma unroll
        for (int nt = 0; nt < 8; nt++) {
            int c = wn + nt * 8 + (lane & 3) * 2;
#pragma unroll
            for (int hh = 0; hh < 2; hh++) {
                int r = r0 + hh * 8;
                if (r >= NN) continue;
                float v0 = acc[m][nt][hh * 2 + 0];
                float v1 = acc[m][nt][hh * 2 + 1];
                if (MODE == 0 || MODE == 1) {
                    v0 += bias[c];
                    v1 += bias[c + 1];
                    float2 mv = *reinterpret_cast<const float2*>(mask + (size_t)r * 128 + c);
                    v0 = fmaxf(v0, 0.f) * mv.x;
                    v1 = fmaxf(v1, 0.f) * mv.y;
                    *reinterpret_cast<float2*>(out + (size_t)r * 128 + c) = make_float2(v0, v1);
                    if (MODE == 0)
                        *reinterpret_cast<__half2*>(h16out + (size_t)r * 128 + c) =
                            __floats2half2_rn(v0, v1);
                } else {
                    if (c < 64) {
                        v0 += bias[c];
                        v1 += bias[c + 1];
                        *reinterpret_cast<float2*>(out + (size_t)r * 64 + c) = make_float2(v0, v1);
                    } else {
                        *reinterpret_cast<__half2*>(h16out + (size_t)r * 64 + (c - 64)) =
                            __floats2half2_rn(v0, v1);
                    }
                }
            }
        }
    }
}

// ---------------- launch ----------------
extern "C" void kernel_launch(void* const* d_in, const int* in_sizes, int n_in,
                              void* d_out, int out_size) {
    const float* x   = (const float*)d_in[0];
    const int*   src = (const int*)d_in[1];
    const int*   dst = (const int*)d_in[2];
    const float* Ws1 = (const float*)d_in[3];
    const float* Wn1 = (const float*)d_in[4];
    const float* b1  = (const float*)d_in[5];
    const float* Ws2 = (const float*)d_in[6];
    const float* Wn2 = (const float*)d_in[7];
    const float* b2  = (const float*)d_in[8];
    const float* Ws3 = (const float*)d_in[9];
    const float* Wn3 = (const float*)d_in[10];
    const float* b3  = (const float*)d_in[11];
    const float* m1  = (const float*)d_in[12];
    const float* m2  = (const float*)d_in[13];
    float* out = (float*)d_out;

    // Real DEVICE addresses (host symbol = ATS shadow trap, see R1)
    float *hA = nullptr, *hB = nullptr, *neigh = nullptr;
    __half* h16 = nullptr;
    __nv_bfloat16 *Bhi = nullptr, *Blo = nullptr;
    cudaGetSymbolAddress((void**)&hA, g_hA);
    cudaGetSymbolAddress((void**)&hB, g_hB);
    cudaGetSymbolAddress((void**)&neigh, g_neigh);
    cudaGetSymbolAddress((void**)&h16, g_h16);
    cudaGetSymbolAddress((void**)&Bhi, g_Bhi);
    cudaGetSymbolAddress((void**)&Blo, g_Blo);

    constexpr int SMEM_GEMM = 8 * 128 * 40 * 2;  // 81920 B
    cudaFuncSetAttribute(sage_mma_kernel<8, true, 0>,
                         cudaFuncAttributeMaxDynamicSharedMemorySize, SMEM_GEMM);
    cudaFuncSetAttribute(sage_mma_kernel<8, true, 1>,
                         cudaFuncAttributeMaxDynamicSharedMemorySize, SMEM_GEMM);
    cudaFuncSetAttribute(sage_mma_kernel<4, false, 2>,
                         cudaFuncAttributeMaxDynamicSharedMemorySize, SMEM_GEMM);

    // ---- weight prep (bf16 hi/lo, transposed) ----
    prep_B_kernel<<<(128 * 256 + 255) / 256, 256>>>(Ws1, Wn1, Bhi, Blo, 0);
    prep_B_kernel<<<(128 * 256 + 255) / 256, 256>>>(Ws2, Wn2, Bhi + 32768, Blo + 32768, 0);
    prep_B_kernel<<<(128 * 128 + 255) / 256, 256>>>(Ws3, Wn3, Bhi + 65536, Blo + 65536, 1);

    // ---- x -> fp16 mirror ----
    conv16_kernel<<<(NN * 64 + 255) / 256, 256>>>(x, h16, NN * 64);

    // ---- CSR build ----
    zero_kernel<<<(NN + 255) / 256, 256>>>();
    count_kernel<<<(EE + 255) / 256, 256>>>(dst);
    scan_partials<<<NBLK, 256>>>();
    scan_bsums<<<1, 256>>>();
    scan_final<<<NBLK, 256>>>();
    fill_kernel<<<(EE + 255) / 256, 256>>>(src, dst);

    int tiles = (NN + 127) / 128;            // 391
    int aggBlocks = (NN * 32 + 255) / 256;

    // ---- layer 1 ----
    agg_h16_kernel<<<aggBlocks, 256>>>(h16, neigh);   // gathers x16
    sage_mma_kernel<8, true, 0><<<tiles, 256, SMEM_GEMM>>>(x, neigh, Bhi, Blo, b1, m1, hA, h16); // writes hA + hA16

    // ---- layer 2 ----
    agg_h16_kernel<<<aggBlocks, 256>>>(h16, neigh);   // gathers hA16
    sage_mma_kernel<8, true, 1><<<tiles, 256, SMEM_GEMM>>>(hA, neigh, Bhi + 32768, Blo + 32768, b2, m2, hB, nullptr);

    // ---- layer 3: project (self fp32 -> hA, proj fp16 -> h16), then aggregate ----
    sage_mma_kernel<4, false, 2><<<tiles, 256, SMEM_GEMM>>>(hB, nullptr, Bhi + 65536, Blo + 65536, b3, nullptr, hA, h16);
    agg3_h16_kernel<<<aggBlocks, 256>>>(h16, hA, out);
}